// round 1
// baseline (speedup 1.0000x reference)
#include <cuda_runtime.h>

// ---------------- scratch (static device memory; no allocs allowed) ----------
__device__ float g_bufA[8 * 64 * 256 * 256];   // 33.5M floats
__device__ float g_bufB[8 * 64 * 256 * 256];   // 33.5M floats
__device__ float g_wT[2304 * 256];             // transposed conv weights (K, Cout)
__device__ float g_scale[256];
__device__ float g_shift[256];

__device__ __forceinline__ float lrelu(float v) { return v >= 0.f ? v : 0.2f * v; }

// ---------------- conv0: 3->64, 3x3 s1 p1, + bias + lrelu (naive) -----------
__global__ void conv0_kernel(const float* __restrict__ x,
                             const float* __restrict__ w,
                             const float* __restrict__ bias,
                             float* __restrict__ out)
{
    int i = blockIdx.x * 256 + threadIdx.x;          // over 8*64*256*256
    int xx = i & 255;
    int y  = (i >> 8) & 255;
    int oc = (i >> 16) & 63;
    int b  = i >> 22;
    float acc = bias[oc];
    const float* wp = w + oc * 27;
#pragma unroll
    for (int c = 0; c < 3; c++) {
        const float* xp = x + ((b * 3 + c) * 256) * 256;
#pragma unroll
        for (int ky = 0; ky < 3; ky++) {
            int iy = y + ky - 1;
            if ((unsigned)iy >= 256u) continue;
#pragma unroll
            for (int kx = 0; kx < 3; kx++) {
                int ix = xx + kx - 1;
                if ((unsigned)ix >= 256u) continue;
                acc = fmaf(__ldg(xp + iy * 256 + ix), wp[c * 9 + ky * 3 + kx], acc);
            }
        }
    }
    out[i] = lrelu(acc);
}

// ---------------- weight transpose: (Cout, K) -> (K, Cout) ------------------
__global__ void transpose_w(const float* __restrict__ w, float* __restrict__ wT,
                            int Cout, int K)
{
    int i = blockIdx.x * 256 + threadIdx.x;
    if (i >= Cout * K) return;
    int k = i / Cout;
    int oc = i - k * Cout;
    wT[i] = w[oc * K + k];
}

// ---------------- generic direct conv as implicit GEMM ----------------------
// Output tile: 128 pixels x BN_ out-channels, K chunked by 8.
// 256 threads: tx = t&15 owns 8 pixels, ty = t>>4 owns TN_ channels.
template <int KH, int KW, int STRIDE, int BN_, int TN_>
__global__ __launch_bounds__(256) void conv_gemm(
    const float* __restrict__ in, const float* __restrict__ wT,
    float* __restrict__ out,
    int Cin, int Cout, int Hin, int Win, int Hout, int Wout)
{
    const int K   = Cin * KH * KW;
    const int HWo = Hout * Wout;
    const int tileP  = blockIdx.x * 128;
    const int ocBase = blockIdx.y * BN_;

    __shared__ float As[8][128];
    __shared__ float Bs[8][BN_];

    const int t  = threadIdx.x;
    const int tx = t & 15;
    const int ty = t >> 4;

    float acc[8][TN_];
#pragma unroll
    for (int i = 0; i < 8; i++)
#pragma unroll
        for (int j = 0; j < TN_; j++) acc[i][j] = 0.f;

    for (int k0 = 0; k0 < K; k0 += 8) {
        // ---- stage A (im2col on the fly): 1024 elems, 4 per thread ----
#pragma unroll
        for (int l = t; l < 1024; l += 256) {
            int kk = l >> 7, pl = l & 127;
            int k  = k0 + kk;
            int c  = k / (KH * KW);
            int r  = k - c * (KH * KW);
            int ky = r / KW;
            int kx = r - ky * KW;
            int p  = tileP + pl;
            int bb = p / HWo;
            int pp = p - bb * HWo;
            int oy = pp / Wout;
            int ox = pp - oy * Wout;
            int iy = oy * STRIDE + ky - 1;
            int ix = ox * STRIDE + kx - 1;
            float v = 0.f;
            if ((unsigned)iy < (unsigned)Hin && (unsigned)ix < (unsigned)Win)
                v = in[((bb * Cin + c) * Hin + iy) * Win + ix];
            As[kk][pl] = v;
        }
        // ---- stage B: BN_*8 elems ----
#pragma unroll
        for (int l = t; l < BN_ * 8; l += 256) {
            int kk = l / BN_, oc = l - kk * BN_;
            Bs[kk][oc] = wT[(k0 + kk) * Cout + ocBase + oc];
        }
        __syncthreads();
#pragma unroll
        for (int kk = 0; kk < 8; kk++) {
            float a[8], bb[TN_];
#pragma unroll
            for (int i = 0; i < 8; i++) a[i] = As[kk][tx * 8 + i];
#pragma unroll
            for (int j = 0; j < TN_; j++) bb[j] = Bs[kk][ty * TN_ + j];
#pragma unroll
            for (int i = 0; i < 8; i++)
#pragma unroll
                for (int j = 0; j < TN_; j++)
                    acc[i][j] = fmaf(a[i], bb[j], acc[i][j]);
        }
        __syncthreads();
    }

    // ---- store raw conv result ----
    int p0 = tileP + tx * 8;
    int bb = p0 / HWo;
    int pp = p0 - bb * HWo;
#pragma unroll
    for (int j = 0; j < TN_; j++) {
        int oc = ocBase + ty * TN_ + j;
        float* op = out + (size_t)(bb * Cout + oc) * HWo + pp;
#pragma unroll
        for (int i = 0; i < 8; i++) op[i] = acc[i][j];
    }
}

// ---------------- BN (training mode): stats -> scale/shift ------------------
__global__ void bn_stats(const float* __restrict__ x,
                         const float* __restrict__ g, const float* __restrict__ bt,
                         int C, int HW, float* __restrict__ scale,
                         float* __restrict__ shift)
{
    int c = blockIdx.x;
    int t = threadIdx.x;
    float s = 0.f, sq = 0.f;
    for (int b = 0; b < 8; b++) {
        const float* p = x + (size_t)(b * C + c) * HW;
        for (int i = t; i < HW; i += 256) {
            float v = p[i];
            s += v;
            sq += v * v;
        }
    }
    __shared__ float ss[256], sqq[256];
    ss[t] = s; sqq[t] = sq;
    __syncthreads();
    for (int o = 128; o > 0; o >>= 1) {
        if (t < o) { ss[t] += ss[t + o]; sqq[t] += sqq[t + o]; }
        __syncthreads();
    }
    if (t == 0) {
        float n = 8.f * (float)HW;
        float m = ss[0] / n;
        float var = sqq[0] / n - m * m;
        float is = rsqrtf(var + 1e-5f);
        float sc = g[c] * is;
        scale[c] = sc;
        shift[c] = bt[c] - m * sc;
    }
}

__global__ void bn_apply(float* __restrict__ x, const float* __restrict__ scale,
                         const float* __restrict__ shift, int C, int HW, int total)
{
    int i = blockIdx.x * 256 + threadIdx.x;
    if (i >= total) return;
    int c = (i / HW) % C;
    float v = fmaf(x[i], scale[c], shift[c]);
    x[i] = v >= 0.f ? v : 0.2f * v;
}

// ---------------- head: router + top-1 expert MLP ---------------------------
// One block (256 threads) per token. fm: (8, 256, 64, 64).
__global__ __launch_bounds__(256) void head_kernel(
    const float* __restrict__ fm,
    const float* __restrict__ wg,      // (256, 12)
    const float* __restrict__ body_w,  // (256, 3072)
    const float* __restrict__ body_b,  // (3072)
    const float* __restrict__ ortho,   // (3072)
    const float* __restrict__ w1,      // (256, 32)
    const float* __restrict__ b1,      // (32)
    const float* __restrict__ w2,      // (32, 1)
    const float* __restrict__ b2,      // (1)
    float* __restrict__ out)           // (8*4096)
{
    int token = blockIdx.x;            // 0..32767
    int b  = token >> 12;
    int pp = token & 4095;
    int t  = threadIdx.x;

    __shared__ float tok[256];
    __shared__ float feat[256];
    __shared__ float lpart[12][8];
    __shared__ int eidx;

    tok[t] = fm[((size_t)(b * 256 + t) << 12) + pp];
    __syncthreads();

    // router logits (argmax of logits == argmax of softmax)
    int lane = t & 31, wrp = t >> 5;
    float tv = tok[t];
#pragma unroll
    for (int e = 0; e < 12; e++) {
        float p = tv * wg[t * 12 + e];
#pragma unroll
        for (int o = 16; o > 0; o >>= 1) p += __shfl_xor_sync(0xffffffffu, p, o);
        if (lane == 0) lpart[e][wrp] = p;
    }
    __syncthreads();
    if (t == 0) {
        int best = 0; float bv = -1e30f;
#pragma unroll
        for (int e = 0; e < 12; e++) {
            float s = 0.f;
#pragma unroll
            for (int w_ = 0; w_ < 8; w_++) s += lpart[e][w_];
            if (s > bv) { bv = s; best = e; }
        }
        eidx = best;
    }
    __syncthreads();
    int e = eidx;

    // selected-expert body column: feat[t] = lrelu(lrelu(tok . body_w[:,e*256+t] + b) * ortho)
    {
        int col = e * 256 + t;
        const float* wcol = body_w + col;
        float acc = body_b[col];
#pragma unroll 8
        for (int d = 0; d < 256; d++) acc = fmaf(tok[d], wcol[(size_t)d * 3072], acc);
        acc = lrelu(acc);
        acc = lrelu(acc * ortho[col]);
        feat[t] = acc;
    }
    __syncthreads();

    // shared classifier: 256 -> 32 (lrelu) -> 1
    if (t < 32) {
        float h = b1[t];
#pragma unroll 8
        for (int k = 0; k < 256; k++) h = fmaf(feat[k], w1[k * 32 + t], h);
        h = lrelu(h);
        float o = h * w2[t];
#pragma unroll
        for (int off = 16; off > 0; off >>= 1) o += __shfl_xor_sync(0xffffffffu, o, off);
        if (t == 0) out[token] = o + b2[0];
    }
}

// ---------------- launch ----------------------------------------------------
extern "C" void kernel_launch(void* const* d_in, const int* in_sizes, int n_in,
                              void* d_out, int out_size)
{
    const float* x        = (const float*)d_in[0];
    const float* conv0_w  = (const float*)d_in[1];
    const float* conv0_b  = (const float*)d_in[2];
    const float* conv1_w  = (const float*)d_in[3];
    const float* bn1_g    = (const float*)d_in[4];
    const float* bn1_b    = (const float*)d_in[5];
    const float* conv2_w  = (const float*)d_in[6];
    const float* bn2_g    = (const float*)d_in[7];
    const float* bn2_b    = (const float*)d_in[8];
    const float* conv3_w  = (const float*)d_in[9];
    const float* bn3_g    = (const float*)d_in[10];
    const float* bn3_b    = (const float*)d_in[11];
    const float* conv4_w  = (const float*)d_in[12];
    const float* bn4_g    = (const float*)d_in[13];
    const float* bn4_b    = (const float*)d_in[14];
    const float* conv5_w  = (const float*)d_in[15];
    const float* bn5_g    = (const float*)d_in[16];
    const float* bn5_b    = (const float*)d_in[17];
    const float* conv6_w  = (const float*)d_in[18];
    const float* bn6_g    = (const float*)d_in[19];
    const float* bn6_b    = (const float*)d_in[20];
    const float* w_gating = (const float*)d_in[21];
    const float* body_w   = (const float*)d_in[22];
    const float* body_b   = (const float*)d_in[23];
    const float* ortho_w  = (const float*)d_in[24];
    const float* cls_w1   = (const float*)d_in[25];
    const float* cls_b1   = (const float*)d_in[26];
    const float* cls_w2   = (const float*)d_in[27];
    const float* cls_b2   = (const float*)d_in[28];
    float* out = (float*)d_out;

    float *A, *Bb, *wT, *sc, *sh;
    cudaGetSymbolAddress((void**)&A,  g_bufA);
    cudaGetSymbolAddress((void**)&Bb, g_bufB);
    cudaGetSymbolAddress((void**)&wT, g_wT);
    cudaGetSymbolAddress((void**)&sc, g_scale);
    cudaGetSymbolAddress((void**)&sh, g_shift);

    // conv0: x -> A  (8,64,256,256), bias+lrelu fused
    conv0_kernel<<<(8 * 64 * 256 * 256) / 256, 256>>>(x, conv0_w, conv0_b, A);

    // conv1: 64->64, 4x4 s2 p1. A -> B (8,64,128,128)
    transpose_w<<<(64 * 1024 + 255) / 256, 256>>>(conv1_w, wT, 64, 1024);
    conv_gemm<4, 4, 2, 64, 4><<<dim3(131072 / 128, 1), 256>>>(
        A, wT, Bb, 64, 64, 256, 256, 128, 128);
    bn_stats<<<64, 256>>>(Bb, bn1_g, bn1_b, 64, 16384, sc, sh);
    bn_apply<<<(8 * 64 * 16384) / 256, 256>>>(Bb, sc, sh, 64, 16384, 8 * 64 * 16384);

    // conv2: 64->128, 3x3 s1 p1. B -> A (8,128,128,128)
    transpose_w<<<(128 * 576 + 255) / 256, 256>>>(conv2_w, wT, 128, 576);
    conv_gemm<3, 3, 1, 128, 8><<<dim3(131072 / 128, 1), 256>>>(
        Bb, wT, A, 64, 128, 128, 128, 128, 128);
    bn_stats<<<128, 256>>>(A, bn2_g, bn2_b, 128, 16384, sc, sh);
    bn_apply<<<(8 * 128 * 16384) / 256, 256>>>(A, sc, sh, 128, 16384, 8 * 128 * 16384);

    // conv3: 128->128, 4x4 s2 p1. A -> B (8,128,64,64)
    transpose_w<<<(128 * 2048 + 255) / 256, 256>>>(conv3_w, wT, 128, 2048);
    conv_gemm<4, 4, 2, 128, 8><<<dim3(32768 / 128, 1), 256>>>(
        A, wT, Bb, 128, 128, 128, 128, 64, 64);
    bn_stats<<<128, 256>>>(Bb, bn3_g, bn3_b, 128, 4096, sc, sh);
    bn_apply<<<(8 * 128 * 4096) / 256, 256>>>(Bb, sc, sh, 128, 4096, 8 * 128 * 4096);

    // conv4: 128->256, 3x3 s1 p1. B -> A (8,256,64,64)
    transpose_w<<<(256 * 1152 + 255) / 256, 256>>>(conv4_w, wT, 256, 1152);
    conv_gemm<3, 3, 1, 128, 8><<<dim3(32768 / 128, 2), 256>>>(
        Bb, wT, A, 128, 256, 64, 64, 64, 64);
    bn_stats<<<256, 256>>>(A, bn4_g, bn4_b, 256, 4096, sc, sh);
    bn_apply<<<(8 * 256 * 4096) / 256, 256>>>(A, sc, sh, 256, 4096, 8 * 256 * 4096);

    // conv5: 256->256, 3x3 s1 p1. A -> B
    transpose_w<<<(256 * 2304 + 255) / 256, 256>>>(conv5_w, wT, 256, 2304);
    conv_gemm<3, 3, 1, 128, 8><<<dim3(32768 / 128, 2), 256>>>(
        A, wT, Bb, 256, 256, 64, 64, 64, 64);
    bn_stats<<<256, 256>>>(Bb, bn5_g, bn5_b, 256, 4096, sc, sh);
    bn_apply<<<(8 * 256 * 4096) / 256, 256>>>(Bb, sc, sh, 256, 4096, 8 * 256 * 4096);

    // conv6: 256->256, 3x3 s1 p1. B -> A
    transpose_w<<<(256 * 2304 + 255) / 256, 256>>>(conv6_w, wT, 256, 2304);
    conv_gemm<3, 3, 1, 128, 8><<<dim3(32768 / 128, 2), 256>>>(
        Bb, wT, A, 256, 256, 64, 64, 64, 64);
    bn_stats<<<256, 256>>>(A, bn6_g, bn6_b, 256, 4096, sc, sh);
    bn_apply<<<(8 * 256 * 4096) / 256, 256>>>(A, sc, sh, 256, 4096, 8 * 256 * 4096);

    // head: router + top-1 expert (only the selected 256-column slice computed)
    head_kernel<<<32768, 256>>>(A, w_gating, body_w, body_b, ortho_w,
                                cls_w1, cls_b1, cls_w2, cls_b2, out);
}